// round 8
// baseline (speedup 1.0000x reference)
#include <cuda_runtime.h>

// x: (2,8,4,256,384) fp32 -> 16 independent DxHxW volumes
#define WD   384
#define HT   256
#define DP   4
#define HW   (HT*WD)          // 98304
#define DHW  (DP*HW)          // 393216
#define NIMG 16

#define OUTW   30             // output columns per warp strip (lanes 1..30)
#define NSTRIP 13             // ceil(384/30)
#define CH     8              // output rows per h-chunk
#define NCH    (HT/CH)        // 32
#define WPB    4              // warps per block
#define HALF_TASKS (NSTRIP*NCH*NIMG)   // 6656 warp-tasks per depth-half
#define NTASK  (2*HALF_TASKS)          // 13312

#define BONUS 10.0f
#define FULL  0xffffffffu

// Per depth-half plane maps (local plane indices 0..2):
// DHALF=0 -> global planes {0,1,2}, depths {0,1}: PM={0,1} PA={0,0} PC={1,2}
// DHALF=1 -> global planes {1,2,3}, depths {2,3}: PM={1,2} PA={0,1} PC={2,2}

template<int DHALF>
__device__ __forceinline__ void run_half(const float* __restrict__ xg,
                                         float* __restrict__ out,
                                         int task, int lane)
{
    constexpr int PM0 = DHALF ? 1 : 0, PM1 = DHALF ? 2 : 1;
    constexpr int PA0 = DHALF ? 0 : 0, PA1 = DHALF ? 1 : 0;
    constexpr int PC0 = DHALF ? 2 : 1, PC1 = DHALF ? 2 : 2;

    const int img   = task / (NSTRIP * NCH);
    const int rem   = task - img * (NSTRIP * NCH);
    const int strip = rem % NSTRIP;
    const int hc    = rem / NSTRIP;

    const int w0   = strip * OUTW;
    const int wout = w0 + lane - 1;
    const bool active = (lane >= 1) && (lane <= 30) && (wout < WD);
    int wcol = wout; if (wcol < 0) wcol = 0; if (wcol > WD-1) wcol = WD-1;

    const int h0 = hc * CH;

    const float* __restrict__ xin = xg + (size_t)img * DHW + DHALF * HW + wcol;

    // 3-slot rolling row window over 3 local planes
    float val[3][3], lf[3][3], rg[3][3], wm[3][2];
    float pend[3];

    #define LOADROW(HR, DST)                                             \
        do {                                                             \
            const float* _p = xin + (HR) * WD;                           \
            (DST)[0] = __ldg(_p);                                        \
            (DST)[1] = __ldg(_p + HW);                                   \
            (DST)[2] = __ldg(_p + 2*HW);                                 \
        } while (0)

    #define COMMIT(RAW, S)                                               \
        do {                                                             \
            _Pragma("unroll")                                            \
            for (int p = 0; p < 3; ++p) {                                \
                float _v = (RAW)[p];                                     \
                val[S][p] = _v;                                          \
                lf[S][p]  = __shfl_up_sync(FULL, _v, 1);                 \
                rg[S][p]  = __shfl_down_sync(FULL, _v, 1);               \
            }                                                            \
            float _h0 = fmaxf(fmaxf(lf[S][0], val[S][0]), rg[S][0]);     \
            float _h1 = fmaxf(fmaxf(lf[S][1], val[S][1]), rg[S][1]);     \
            float _h2 = fmaxf(fmaxf(lf[S][2], val[S][2]), rg[S][2]);     \
            /* depth NMS windows (clamped duplicates are max-neutral) */ \
            float _hA0 = (PA0==0?_h0:(PA0==1?_h1:_h2));                  \
            float _hM0 = (PM0==0?_h0:(PM0==1?_h1:_h2));                  \
            float _hC0 = (PC0==0?_h0:(PC0==1?_h1:_h2));                  \
            float _hA1 = (PA1==0?_h0:(PA1==1?_h1:_h2));                  \
            float _hM1 = (PM1==0?_h0:(PM1==1?_h1:_h2));                  \
            float _hC1 = (PC1==0?_h0:(PC1==1?_h1:_h2));                  \
            wm[S][0] = fmaxf(fmaxf(_hA0, _hM0), _hC0);                   \
            wm[S][1] = fmaxf(fmaxf(_hA1, _hM1), _hC1);                   \
        } while (0)

    // ---- prologue ----
    {
        float ra[3], rb[3];
        int r_up = h0 - 1; if (r_up < 0) r_up = 0;
        LOADROW(r_up, ra);
        LOADROW(h0,  rb);
        COMMIT(ra, 0);
        COMMIT(rb, 1);
        int r_dn = h0 + 1; if (r_dn > HT-1) r_dn = HT-1;
        LOADROW(r_dn, pend);
    }

    float* __restrict__ oc0 = out + (size_t)img * 3 * DHW;
    float* __restrict__ oy  = out + (size_t)NIMG * 3 * DHW + (size_t)img * DHW;

    int obase = h0 * WD + wout;

    #pragma unroll
    for (int i = 0; i < CH; ++i) {
        const int h  = h0 + i;
        const int sU = i % 3;
        const int sM = (i + 1) % 3;
        const int sD = (i + 2) % 3;

        float tmp[3];
        #pragma unroll
        for (int p = 0; p < 3; ++p) tmp[p] = pend[p];
        int rn = h + 2; if (rn > HT-1) rn = HT-1;
        LOADROW(rn, pend);
        COMMIT(tmp, sD);

        #pragma unroll
        for (int j = 0; j < 2; ++j) {
            constexpr int JM[2] = {PM0, PM1};
            constexpr int JA[2] = {PA0, PA1};
            constexpr int JC[2] = {PC0, PC1};
            const int m = JM[j], a = JA[j], c = JC[j];
            const int dglob = DHALF * 2 + j;

            const float xc = val[sM][m];

            const float b0 = 0.5f * (rg[sM][m] - lf[sM][m]);      // dx
            const float b1 = 0.5f * (val[sD][m] - val[sU][m]);    // dy
            const float b2 = 0.5f * (val[sM][a] - val[sM][c]);    // ds (flipped)

            const float dxx = rg[sM][m]  - 2.0f*xc + lf[sM][m];
            const float dyy = val[sD][m] - 2.0f*xc + val[sU][m];
            const float dss = val[sM][c] - 2.0f*xc + val[sM][a];
            const float dxy = 0.25f * ( lf[sU][m] - rg[sU][m] - lf[sD][m] + rg[sD][m]);
            const float dys = 0.25f * (-val[sU][a] + val[sD][a] + val[sU][c] - val[sD][c]);
            const float dxs = 0.25f * (-lf[sM][a] + rg[sM][a] + lf[sM][c] - rg[sM][c]);

            const float mx = fmaxf(fmaxf(wm[sU][j], wm[sM][j]), wm[sD][j]);
            const bool nms = (xc == mx);

            const float c00 = dyy*dss - dys*dys;
            const float c01 = dxs*dys - dxy*dss;
            const float c02 = dxy*dys - dxs*dyy;
            const float c11 = dxx*dss - dxs*dxs;
            const float c12 = dxy*dxs - dxx*dys;
            const float c22 = dxx*dyy - dxy*dxy;
            const float det = dxx*c00 + dxy*c01 + dxs*c02;

            const bool ok = nms && (det != 0.0f);
            const float invdet = __fdividef(1.0f, (det == 0.0f) ? 1.0f : det);

            const float u0 = (c00*b0 + c01*b1 + c02*b2) * invdet;
            const float u1 = (c01*b0 + c11*b1 + c12*b2) * invdet;
            const float u2 = (c02*b0 + c12*b1 + c22*b2) * invdet;

            float d0 = ok ? -u0 : 0.0f;
            float d1 = ok ? -u1 : 0.0f;
            float d2 = ok ? -u2 : 0.0f;

            const bool small = fmaxf(fmaxf(fabsf(d0), fabsf(d1)), fabsf(d2)) <= 0.7f;
            d0 = small ? d0 : 0.0f;
            d1 = small ? d1 : 0.0f;
            d2 = small ? d2 : 0.0f;

            const float dE = 0.5f * (b0*d0 + b1*d1 + b2*d2);

            if (active) {
                const int o = obase + dglob * HW;
                oc0[o + 0*DHW] = (float)dglob + d2;
                oc0[o + 1*DHW] = (float)wout + d0;
                oc0[o + 2*DHW] = (float)h + d1;
                oy [o]         = xc + dE + (ok ? BONUS : 0.0f);
            }
        }
        obase += WD;
    }
    #undef LOADROW
    #undef COMMIT
}

__global__ __launch_bounds__(128, 8)
void cqi_kernel(const float* __restrict__ xg, float* __restrict__ out)
{
    const int gw   = blockIdx.x * WPB + (threadIdx.x >> 5);
    const int lane = threadIdx.x & 31;
    if (gw < HALF_TASKS)
        run_half<0>(xg, out, gw, lane);
    else
        run_half<1>(xg, out, gw - HALF_TASKS, lane);
}

extern "C" void kernel_launch(void* const* d_in, const int* in_sizes, int n_in,
                              void* d_out, int out_size)
{
    const float* x = (const float*)d_in[0];
    float* out = (float*)d_out;
    dim3 block(WPB * 32, 1, 1);
    dim3 grid(NTASK / WPB, 1, 1);
    cqi_kernel<<<grid, block>>>(x, out);
}